// round 4
// baseline (speedup 1.0000x reference)
#include <cuda_runtime.h>
#include <math.h>

// ---------------- scratch (no allocation allowed) ----------------
__device__ float  g_bufA[32u*64*128*128];   // 8.39M floats
__device__ float  g_bufB[32u*64*128*128];   // 8.39M floats
__device__ float  g_bufC[32u*64*32*32];     // 2.10M floats (dec resblock temp)
__device__ int    g_idx[32768];
__device__ float  g_counts[2048];
__device__ float  g_cnorm[2048];
__device__ double g_vq_ss;
__device__ double g_recon_ss;

// ---------------- helpers ----------------
__device__ __forceinline__ float block_sum(float v) {
    __shared__ float sh[256];
    int t = threadIdx.x;
    sh[t] = v; __syncthreads();
    #pragma unroll
    for (int s = 128; s > 0; s >>= 1) {
        if (t < s) sh[t] += sh[t + s];
        __syncthreads();
    }
    return sh[0];
}

__global__ void init_k() {
    int i = blockIdx.x * 256 + threadIdx.x;
    if (i < 2048) g_counts[i] = 0.f;
    if (i == 0) { g_vq_ss = 0.0; g_recon_ss = 0.0; }
}

// ---------------- conv k=4 s=2 p=1, fused bias+BN(+ReLU), COUT=64 ----------------
template<int CIN, bool RELU>
__global__ __launch_bounds__(256) void conv4s2_k(
    const float* __restrict__ in, int Hin, int Win,
    float* __restrict__ out, int Hout, int Wout,
    const float* __restrict__ w, const float* __restrict__ bias,
    const float* __restrict__ bnp)
{
    __shared__ float sw[CIN * 16];
    const int co = blockIdx.y, n = blockIdx.z;
    for (int i = threadIdx.x; i < CIN * 16; i += 256) sw[i] = w[co * CIN * 16 + i];
    __syncthreads();
    int sp = blockIdx.x * 256 + threadIdx.x;
    int ho = sp / Wout, wo = sp - ho * Wout;
    const int HWin = Hin * Win;
    const float* inp = in + ((size_t)n * CIN) * HWin;
    float acc = 0.f;
    const int hb = ho * 2 - 1, wb = wo * 2 - 1;
    for (int ci = 0; ci < CIN; ++ci) {
        const float* bp = inp + ci * HWin;
        const float* wp = sw + ci * 16;
        #pragma unroll
        for (int kh = 0; kh < 4; ++kh) {
            int hi = hb + kh;
            if ((unsigned)hi < (unsigned)Hin) {
                const float* rp = bp + hi * Win;
                #pragma unroll
                for (int kw = 0; kw < 4; ++kw) {
                    int wi = wb + kw;
                    if ((unsigned)wi < (unsigned)Win)
                        acc += rp[wi] * wp[kh * 4 + kw];
                }
            }
        }
    }
    float r = acc + bias[co];
    float g = bnp[co], bt = bnp[64 + co], m = bnp[128 + co], vv = bnp[192 + co];
    r = (r - m) * (g * rsqrtf(vv + 1e-5f)) + bt;
    if (RELU) r = fmaxf(r, 0.f);
    out[((size_t)n * 64 + co) * (Hout * Wout) + sp] = r;
}

// ---------------- conv 3x3 s=1 p=1, CIN=COUT=64 ----------------
template<bool PRERELU, bool HAS_BN>
__global__ __launch_bounds__(256) void conv3x3_k(
    const float* __restrict__ in, float* __restrict__ out, int H, int W,
    const float* __restrict__ w, const float* __restrict__ bias,
    const float* __restrict__ bnp)
{
    __shared__ float sw[64 * 9];
    const int co = blockIdx.y, n = blockIdx.z;
    for (int i = threadIdx.x; i < 576; i += 256) sw[i] = w[co * 576 + i];
    __syncthreads();
    int sp = blockIdx.x * 256 + threadIdx.x;
    int ho = sp / W, wo = sp - ho * W;
    const int HW = H * W;
    const float* inp = in + ((size_t)n * 64) * HW;
    float acc = 0.f;
    for (int ci = 0; ci < 64; ++ci) {
        const float* bp = inp + ci * HW;
        const float* wp = sw + ci * 9;
        #pragma unroll
        for (int kh = 0; kh < 3; ++kh) {
            int hi = ho - 1 + kh;
            if ((unsigned)hi < (unsigned)H) {
                const float* rp = bp + hi * W;
                #pragma unroll
                for (int kw = 0; kw < 3; ++kw) {
                    int wi = wo - 1 + kw;
                    if ((unsigned)wi < (unsigned)W) {
                        float v = rp[wi];
                        if (PRERELU) v = fmaxf(v, 0.f);
                        acc += v * wp[kh * 3 + kw];
                    }
                }
            }
        }
    }
    float r = acc + bias[co];
    if (HAS_BN) {
        float g = bnp[co], bt = bnp[64 + co], m = bnp[128 + co], vv = bnp[192 + co];
        r = (r - m) * (g * rsqrtf(vv + 1e-5f)) + bt;
    }
    out[((size_t)n * 64 + co) * HW + sp] = r;
}

// ---------------- conv 1x1, CIN=COUT=64, optional pre-ReLU/BN/residual ----------------
template<bool PRERELU, bool HAS_BN, bool RES>
__global__ __launch_bounds__(256) void conv1x1_k(
    const float* __restrict__ in, const float* __restrict__ res,
    float* __restrict__ out, int HW,
    const float* __restrict__ w, const float* __restrict__ bias,
    const float* __restrict__ bnp)
{
    __shared__ float sw[64];
    const int co = blockIdx.y, n = blockIdx.z;
    if (threadIdx.x < 64) sw[threadIdx.x] = w[co * 64 + threadIdx.x];
    __syncthreads();
    int sp = blockIdx.x * 256 + threadIdx.x;
    const float* inp = in + ((size_t)n * 64) * HW + sp;
    float acc = 0.f;
    #pragma unroll 8
    for (int ci = 0; ci < 64; ++ci) {
        float v = inp[(size_t)ci * HW];
        if (PRERELU) v = fmaxf(v, 0.f);
        acc += v * sw[ci];
    }
    float r = acc + bias[co];
    if (HAS_BN) {
        float g = bnp[co], bt = bnp[64 + co], m = bnp[128 + co], vv = bnp[192 + co];
        r = (r - m) * (g * rsqrtf(vv + 1e-5f)) + bt;
    }
    if (RES) r += res[((size_t)n * 64 + co) * HW + sp];
    out[((size_t)n * 64 + co) * HW + sp] = r;
}

// ---------------- VQ ----------------
__global__ void cnorm_k(const float* __restrict__ cb) {
    int k = blockIdx.x * 256 + threadIdx.x;
    if (k < 2048) {
        float s = 0.f;
        #pragma unroll
        for (int d = 0; d < 64; ++d) { float c = cb[k * 64 + d]; s += c * c; }
        g_cnorm[k] = s;
    }
}

__global__ __launch_bounds__(256) void vq_assign_k(
    const float* __restrict__ z, const float* __restrict__ cb)
{
    __shared__ float4 sc[128 * 16];
    __shared__ float  sn[128];
    int row = blockIdx.x * 256 + threadIdx.x;   // 0..32767
    int b = row >> 10, hw = row & 1023;
    float zr[64];
    const float* zp = z + ((size_t)b * 64) * 1024 + hw;
    #pragma unroll
    for (int d = 0; d < 64; ++d) zr[d] = zp[d * 1024];
    float best = 3.4e38f; int bi = 0;
    const float4* cb4 = (const float4*)cb;
    for (int k0 = 0; k0 < 2048; k0 += 128) {
        __syncthreads();
        for (int i = threadIdx.x; i < 128 * 16; i += 256) sc[i] = cb4[k0 * 16 + i];
        for (int i = threadIdx.x; i < 128; i += 256) sn[i] = g_cnorm[k0 + i];
        __syncthreads();
        for (int kk = 0; kk < 128; ++kk) {
            const float4* cp = sc + kk * 16;
            float dot = 0.f;
            #pragma unroll
            for (int j = 0; j < 16; ++j) {
                float4 c = cp[j];
                dot += zr[4 * j] * c.x + zr[4 * j + 1] * c.y
                     + zr[4 * j + 2] * c.z + zr[4 * j + 3] * c.w;
            }
            float dist = sn[kk] - 2.f * dot;   // ||z||^2 omitted (argmin-invariant)
            if (dist < best) { best = dist; bi = k0 + kk; }
        }
    }
    g_idx[row] = bi;
}

__global__ __launch_bounds__(256) void vq_gather_k(
    const float* __restrict__ z, const float* __restrict__ cb,
    float* __restrict__ quant)
{
    int gid = blockIdx.x * 256 + threadIdx.x;   // over 32*64*1024
    int b = gid >> 16;
    int rem = gid & 65535;
    int d = rem >> 10;
    int hw = rem & 1023;
    int k = g_idx[(b << 10) + hw];
    float q = cb[k * 64 + d];
    float zv = z[gid];
    quant[gid] = q;                 // straight-through forward value == q
    float diff = q - zv;
    float s = block_sum(diff * diff);
    if (threadIdx.x == 0) atomicAdd(&g_vq_ss, (double)s);
}

__global__ void vq_counts_k() {
    int i = blockIdx.x * 256 + threadIdx.x;
    if (i < 32768) atomicAdd(&g_counts[g_idx[i]], 1.0f);
}

// ---------------- conv-transpose k=4 s=2 p=1, CIN=64 ----------------
template<int COUT, bool PRERELU, bool TANH_LOSS>
__global__ __launch_bounds__(256) void convt_k(
    const float* __restrict__ in, int Hin, int Win,
    float* __restrict__ out, int Hout, int Wout,
    const float* __restrict__ w, const float* __restrict__ bias,
    const float* __restrict__ xref)
{
    __shared__ float sw[64 * 16];   // [ci][kh*4+kw] for this co
    const int co = blockIdx.y, n = blockIdx.z;
    for (int i = threadIdx.x; i < 64 * 16; i += 256) {
        int ci = i >> 4, t = i & 15;
        sw[i] = w[(ci * COUT + co) * 16 + t];
    }
    __syncthreads();
    int sp = blockIdx.x * 256 + threadIdx.x;
    int ho = sp / Wout, wo = sp - ho * Wout;
    // taps: ho = 2*hi - 1 + kh, kh parity == (ho+1)&1
    int kh0 = (ho + 1) & 1; int hi0 = (ho + 1 - kh0) >> 1; int kh1 = kh0 + 2; int hi1 = hi0 - 1;
    int kw0 = (wo + 1) & 1; int wi0 = (wo + 1 - kw0) >> 1; int kw1 = kw0 + 2; int wi1 = wi0 - 1;
    bool vh0 = (unsigned)hi0 < (unsigned)Hin, vh1 = (unsigned)hi1 < (unsigned)Hin;
    bool vw0 = (unsigned)wi0 < (unsigned)Win, vw1 = (unsigned)wi1 < (unsigned)Win;
    const int HWin = Hin * Win;
    const float* inp = in + ((size_t)n * 64) * HWin;
    int o00 = hi0 * Win + wi0, o01 = hi0 * Win + wi1;
    int o10 = hi1 * Win + wi0, o11 = hi1 * Win + wi1;
    int t00 = kh0 * 4 + kw0, t01 = kh0 * 4 + kw1;
    int t10 = kh1 * 4 + kw0, t11 = kh1 * 4 + kw1;
    bool m00 = vh0 && vw0, m01 = vh0 && vw1, m10 = vh1 && vw0, m11 = vh1 && vw1;
    float acc = 0.f;
    for (int ci = 0; ci < 64; ++ci) {
        const float* bp = inp + ci * HWin;
        const float* wp = sw + ci * 16;
        float v;
        if (m00) { v = bp[o00]; if (PRERELU) v = fmaxf(v, 0.f); acc += v * wp[t00]; }
        if (m01) { v = bp[o01]; if (PRERELU) v = fmaxf(v, 0.f); acc += v * wp[t01]; }
        if (m10) { v = bp[o10]; if (PRERELU) v = fmaxf(v, 0.f); acc += v * wp[t10]; }
        if (m11) { v = bp[o11]; if (PRERELU) v = fmaxf(v, 0.f); acc += v * wp[t11]; }
    }
    float r = acc + bias[co];
    size_t oidx = ((size_t)n * COUT + co) * ((size_t)Hout * Wout) + sp;
    if (TANH_LOSS) {
        r = tanhf(r);
        out[oidx] = r;
        float dfl = r - xref[oidx];
        float s = block_sum(dfl * dfl);
        if (threadIdx.x == 0) atomicAdd(&g_recon_ss, (double)s);
    } else {
        out[oidx] = fmaxf(r, 0.f);
    }
}

// ---------------- finalize: perplexity + total loss ----------------
__global__ void finalize_k(float* __restrict__ out2) {
    float s = 0.f;
    for (int k = threadIdx.x; k < 2048; k += 256) {
        float p = g_counts[k] * (1.0f / 32768.0f);
        s += p * logf(p + 1e-10f);
    }
    float tot = block_sum(s);
    if (threadIdx.x == 0) {
        float perp = expf(-tot);
        float loss = (float)(g_recon_ss / 31457280.0 + 1.25 * (g_vq_ss / 2097152.0));
        out2[0] = loss;
        out2[1] = perp;
    }
}

// ---------------- launcher ----------------
extern "C" void kernel_launch(void* const* d_in, const int* in_sizes, int n_in,
                              void* d_out, int out_size) {
    const float* x          = (const float*)d_in[0];
    const float* ew1        = (const float*)d_in[1];
    const float* eb1        = (const float*)d_in[2];
    const float* ew2        = (const float*)d_in[3];
    const float* eb2        = (const float*)d_in[4];
    const float* ew3        = (const float*)d_in[5];
    const float* eb3        = (const float*)d_in[6];
    const float* enc_bn     = (const float*)d_in[7];
    const float* enc_res_w3 = (const float*)d_in[8];
    const float* enc_res_b3 = (const float*)d_in[9];
    const float* enc_res_w1 = (const float*)d_in[10];
    const float* enc_res_b1 = (const float*)d_in[11];
    const float* enc_res_bn = (const float*)d_in[12];
    const float* enc_out_w  = (const float*)d_in[13];
    const float* enc_out_b  = (const float*)d_in[14];
    const float* codebook   = (const float*)d_in[15];
    const float* dec_in_w   = (const float*)d_in[16];
    const float* dec_in_b   = (const float*)d_in[17];
    const float* dec_res_w3 = (const float*)d_in[18];
    const float* dec_res_b3 = (const float*)d_in[19];
    const float* dec_res_w1 = (const float*)d_in[20];
    const float* dec_res_b1 = (const float*)d_in[21];
    const float* dec_res_bn = (const float*)d_in[22];
    const float* dt_w1      = (const float*)d_in[23];
    const float* dt_b1      = (const float*)d_in[24];
    const float* dt_w2      = (const float*)d_in[25];
    const float* dt_b2      = (const float*)d_in[26];
    const float* dt_w3      = (const float*)d_in[27];
    const float* dt_b3      = (const float*)d_in[28];

    void *pa, *pb, *pc;
    cudaGetSymbolAddress(&pa, g_bufA);
    cudaGetSymbolAddress(&pb, g_bufB);
    cudaGetSymbolAddress(&pc, g_bufC);
    float* A  = (float*)pa;
    float* Bb = (float*)pb;
    float* Cc = (float*)pc;
    float* out = (float*)d_out;

    init_k<<<8, 256>>>();

    // ---- Encoder ----
    conv4s2_k<15, true ><<<dim3(64, 64, 32), 256>>>(x, 256, 256, A, 128, 128, ew1, eb1, enc_bn);
    conv4s2_k<64, true ><<<dim3(16, 64, 32), 256>>>(A, 128, 128, Bb, 64, 64, ew2, eb2, enc_bn + 256);
    conv4s2_k<64, false><<<dim3(4, 64, 32), 256>>>(Bb, 64, 64, A, 32, 32, ew3, eb3, enc_bn + 512);
    for (int i = 0; i < 4; ++i) {
        conv3x3_k<true, true><<<dim3(4, 64, 32), 256>>>(
            A, Bb, 32, 32, enc_res_w3 + (size_t)i * 36864, enc_res_b3 + i * 64,
            enc_res_bn + i * 512);
        conv1x1_k<true, true, true><<<dim3(4, 64, 32), 256>>>(
            Bb, A, A, 1024, enc_res_w1 + (size_t)i * 4096, enc_res_b1 + i * 64,
            enc_res_bn + i * 512 + 256);
    }
    conv1x1_k<false, false, false><<<dim3(4, 64, 32), 256>>>(
        A, nullptr, Bb, 1024, enc_out_w, enc_out_b, nullptr);   // z -> Bb

    // ---- VQ ----
    cnorm_k<<<8, 256>>>(codebook);
    vq_assign_k<<<128, 256>>>(Bb, codebook);
    vq_gather_k<<<8192, 256>>>(Bb, codebook, A);                // quant -> A
    vq_counts_k<<<128, 256>>>();

    // ---- Decoder ----
    conv3x3_k<false, false><<<dim3(4, 64, 32), 256>>>(A, Bb, 32, 32, dec_in_w, dec_in_b, nullptr);
    for (int i = 0; i < 4; ++i) {
        conv3x3_k<true, true><<<dim3(4, 64, 32), 256>>>(
            Bb, Cc, 32, 32, dec_res_w3 + (size_t)i * 36864, dec_res_b3 + i * 64,
            dec_res_bn + i * 512);
        conv1x1_k<true, true, true><<<dim3(4, 64, 32), 256>>>(
            Cc, Bb, Bb, 1024, dec_res_w1 + (size_t)i * 4096, dec_res_b1 + i * 64,
            dec_res_bn + i * 512 + 256);
    }
    convt_k<64, true,  false><<<dim3(16, 64, 32), 256>>>(Bb, 32, 32, A, 64, 64, dt_w1, dt_b1, nullptr);
    convt_k<64, false, false><<<dim3(64, 64, 32), 256>>>(A, 64, 64, Bb, 128, 128, dt_w2, dt_b2, nullptr);
    convt_k<15, false, true ><<<dim3(256, 15, 32), 256>>>(Bb, 128, 128, out, 256, 256, dt_w3, dt_b3, x);

    finalize_k<<<1, 256>>>(out + (out_size - 2));
}

// round 6
// speedup vs baseline: 4.3276x; 4.3276x over previous
#include <cuda_runtime.h>
#include <math.h>

// ---------------- scratch (no allocation allowed) ----------------
__device__ float  g_bufA[32u*64*128*128];   // 8.39M floats
__device__ float  g_bufB[32u*64*128*128];   // 8.39M floats
__device__ float  g_bufC[32u*64*32*32];     // 2.10M floats
__device__ int    g_idx[32768];
__device__ float  g_counts[2048];
__device__ float  g_cnorm[2048];
__device__ double g_vq_ss;
__device__ double g_recon_ss;

// ---------------- helpers ----------------
__device__ __forceinline__ float block_sum(float v) {
    __shared__ float sh[256];
    int t = threadIdx.x;
    sh[t] = v; __syncthreads();
    #pragma unroll
    for (int s = 128; s > 0; s >>= 1) {
        if (t < s) sh[t] += sh[t + s];
        __syncthreads();
    }
    return sh[0];
}

__global__ void init_k() {
    int i = blockIdx.x * 256 + threadIdx.x;
    if (i < 2048) g_counts[i] = 0.f;
    if (i == 0) { g_vq_ss = 0.0; g_recon_ss = 0.0; }
}

// =====================================================================
// conv 3x3 s1 p1, 64->64, H=W=32. Register-tiled: block = 4 rows x 32
// cols x 64 co; thread = 4 spatial x 8 co.
// =====================================================================
template<bool PRERELU, bool HAS_BN>
__global__ __launch_bounds__(256) void conv3x3_t(
    const float* __restrict__ in, float* __restrict__ out,
    const float* __restrict__ w, const float* __restrict__ bias,
    const float* __restrict__ bnp)
{
    __shared__ float sIn[8 * 6 * 35];      // [ci8][row6][col35(pad)]
    __shared__ float sW [8 * 9 * 68];      // [ci8][tap9][co 68-pad]
    const int t = threadIdx.x, ty = t >> 5, tx = t & 31;
    const int row = tx >> 3, col4 = (tx & 7) << 2;
    const int n = blockIdx.y, r0 = blockIdx.x << 2;
    const float* inb = in + (size_t)n * 64 * 1024;
    float acc[4][8];
    #pragma unroll
    for (int j = 0; j < 4; ++j)
        #pragma unroll
        for (int i = 0; i < 8; ++i) acc[j][i] = 0.f;

    for (int ci0 = 0; ci0 < 64; ci0 += 8) {
        __syncthreads();
        for (int i = t; i < 8 * 6 * 34; i += 256) {
            int ci = i / 204, r2 = i - ci * 204, rr = r2 / 34, cc = r2 - rr * 34;
            int gr = r0 - 1 + rr, gc = cc - 1;
            float v = 0.f;
            if ((unsigned)gr < 32u && (unsigned)gc < 32u) {
                v = inb[(ci0 + ci) * 1024 + gr * 32 + gc];
                if (PRERELU) v = fmaxf(v, 0.f);
            }
            sIn[ci * 210 + rr * 35 + cc] = v;
        }
        for (int i = t; i < 8 * 9 * 64; i += 256) {
            int co = i / 72, r2 = i - co * 72, ci = r2 / 9, tap = r2 - ci * 9;
            sW[ci * 612 + tap * 68 + co] = w[co * 576 + (ci0 + ci) * 9 + tap];
        }
        __syncthreads();
        #pragma unroll
        for (int ci = 0; ci < 8; ++ci) {
            const float* sIb = sIn + ci * 210 + row * 35 + col4;
            const float* sWb = sW + ci * 612 + ty * 8;
            #pragma unroll
            for (int kh = 0; kh < 3; ++kh) {
                #pragma unroll
                for (int kw = 0; kw < 3; ++kw) {
                    float wv[8];
                    *(float4*)&wv[0] = *(const float4*)(sWb + (kh * 3 + kw) * 68);
                    *(float4*)&wv[4] = *(const float4*)(sWb + (kh * 3 + kw) * 68 + 4);
                    float vv[4];
                    #pragma unroll
                    for (int j = 0; j < 4; ++j) vv[j] = sIb[kh * 35 + kw + j];
                    #pragma unroll
                    for (int j = 0; j < 4; ++j)
                        #pragma unroll
                        for (int i = 0; i < 8; ++i) acc[j][i] += vv[j] * wv[i];
                }
            }
        }
    }
    const int orow = r0 + row;
    #pragma unroll
    for (int i = 0; i < 8; ++i) {
        int co = ty * 8 + i;
        float b = bias[co];
        float r[4];
        #pragma unroll
        for (int j = 0; j < 4; ++j) r[j] = acc[j][i] + b;
        if (HAS_BN) {
            float s = bnp[co] * rsqrtf(bnp[192 + co] + 1e-5f);
            float m = bnp[128 + co], bt = bnp[64 + co];
            #pragma unroll
            for (int j = 0; j < 4; ++j) r[j] = (r[j] - m) * s + bt;
        }
        float4 o; o.x = r[0]; o.y = r[1]; o.z = r[2]; o.w = r[3];
        *(float4*)&out[((size_t)n * 64 + co) * 1024 + orow * 32 + col4] = o;
    }
}

// =====================================================================
// conv 1x1, 64->64, HW=1024. Block = 128 spatial x 64 co.
// =====================================================================
template<bool PRERELU, bool HAS_BN, bool RES>
__global__ __launch_bounds__(256) void conv1x1_t(
    const float* __restrict__ in, const float* __restrict__ res,
    float* __restrict__ out,
    const float* __restrict__ w, const float* __restrict__ bias,
    const float* __restrict__ bnp)
{
    __shared__ float sIn[32 * 128];
    __shared__ float sW [64 * 68];
    const int t = threadIdx.x, ty = t >> 5, tx = t & 31;
    const int n = blockIdx.y, sp0 = blockIdx.x * 128;
    for (int i = t; i < 4096; i += 256) {
        int co = i >> 6, ci = i & 63;
        sW[ci * 68 + co] = w[co * 64 + ci];
    }
    float acc[4][8];
    #pragma unroll
    for (int j = 0; j < 4; ++j)
        #pragma unroll
        for (int i = 0; i < 8; ++i) acc[j][i] = 0.f;
    const float* inb = in + (size_t)n * 64 * 1024 + sp0;
    for (int ch = 0; ch < 2; ++ch) {
        __syncthreads();
        for (int i = t; i < 4096; i += 256) {
            int ci = i >> 7, s = i & 127;
            float v = inb[(ch * 32 + ci) * 1024 + s];
            if (PRERELU) v = fmaxf(v, 0.f);
            sIn[i] = v;
        }
        __syncthreads();
        #pragma unroll 4
        for (int ci = 0; ci < 32; ++ci) {
            float4 v = *(const float4*)&sIn[ci * 128 + tx * 4];
            float wv[8];
            *(float4*)&wv[0] = *(const float4*)&sW[(ch * 32 + ci) * 68 + ty * 8];
            *(float4*)&wv[4] = *(const float4*)&sW[(ch * 32 + ci) * 68 + ty * 8 + 4];
            float vv[4] = {v.x, v.y, v.z, v.w};
            #pragma unroll
            for (int j = 0; j < 4; ++j)
                #pragma unroll
                for (int i = 0; i < 8; ++i) acc[j][i] += vv[j] * wv[i];
        }
    }
    #pragma unroll
    for (int i = 0; i < 8; ++i) {
        int co = ty * 8 + i;
        float b = bias[co];
        float r[4];
        #pragma unroll
        for (int j = 0; j < 4; ++j) r[j] = acc[j][i] + b;
        if (HAS_BN) {
            float s = bnp[co] * rsqrtf(bnp[192 + co] + 1e-5f);
            float m = bnp[128 + co], bt = bnp[64 + co];
            #pragma unroll
            for (int j = 0; j < 4; ++j) r[j] = (r[j] - m) * s + bt;
        }
        size_t oi = ((size_t)n * 64 + co) * 1024 + sp0 + tx * 4;
        if (RES) {
            float4 rv = *(const float4*)&res[oi];
            r[0] += rv.x; r[1] += rv.y; r[2] += rv.z; r[3] += rv.w;
        }
        float4 o; o.x = r[0]; o.y = r[1]; o.z = r[2]; o.w = r[3];
        *(float4*)&out[oi] = o;
    }
}

// =====================================================================
// conv k4 s2 p1 -> 64 co, BN fused. Input parity-split in SMEM so
// stride-2 taps read unit-stride. Tile = 128 outputs (full rows) x 64 co.
// =====================================================================
template<int CIN, int OW, int C, bool RELU>
__global__ __launch_bounds__(256) void conv4s2_t(
    const float* __restrict__ in, float* __restrict__ out,
    const float* __restrict__ w, const float* __restrict__ bias,
    const float* __restrict__ bnp)
{
    constexpr int R = 128 / OW, CPR = OW / 4, HIN = OW * 2;
    constexpr int NR = 2 * R + 2, P = OW + 1, CIST = NR * 2 * P;
    __shared__ float sIn[C * CIST];          // [ci][row NR][parity2][P]
    __shared__ float sW [C * 16 * 68];       // [ci][tap16][co 68-pad]
    const int t = threadIdx.x, ty = t >> 5, tx = t & 31;
    const int row = tx / CPR, col4 = (tx % CPR) * 4;
    const int n = blockIdx.y, r0 = blockIdx.x * R;
    const float* inb = in + (size_t)n * CIN * HIN * HIN;
    float acc[4][8];
    #pragma unroll
    for (int j = 0; j < 4; ++j)
        #pragma unroll
        for (int i = 0; i < 8; ++i) acc[j][i] = 0.f;

    for (int ci0 = 0; ci0 < CIN; ci0 += C) {
        __syncthreads();
        for (int i = t; i < C * CIST; i += 256) {
            int ci = i / CIST, r2 = i - ci * CIST;
            int rr = r2 / (2 * P), r3 = r2 - rr * 2 * P;
            int p = r3 / P, cc = r3 - p * P;
            int gr = 2 * r0 - 1 + rr;
            int gc = 2 * cc - p;
            float v = 0.f;
            if ((unsigned)gr < (unsigned)HIN && (unsigned)gc < (unsigned)HIN)
                v = inb[(ci0 + ci) * (HIN * HIN) + gr * HIN + gc];
            sIn[i] = v;
        }
        for (int i = t; i < C * 16 * 64; i += 256) {
            int co = i / (C * 16), r2 = i - co * C * 16, ci = r2 >> 4, tap = r2 & 15;
            sW[ci * 1088 + tap * 68 + co] = w[(co * CIN + ci0 + ci) * 16 + tap];
        }
        __syncthreads();
        #pragma unroll
        for (int ci = 0; ci < C; ++ci) {
            const float* sIb = sIn + ci * CIST + (2 * row) * (2 * P) + col4;
            const float* sWb = sW + ci * 1088 + ty * 8;
            #pragma unroll
            for (int kh = 0; kh < 4; ++kh) {
                #pragma unroll
                for (int kw = 0; kw < 4; ++kw) {
                    const float* ip = sIb + kh * (2 * P) + ((kw & 1) ^ 1) * P + (kw >> 1);
                    float wv[8];
                    *(float4*)&wv[0] = *(const float4*)(sWb + (kh * 4 + kw) * 68);
                    *(float4*)&wv[4] = *(const float4*)(sWb + (kh * 4 + kw) * 68 + 4);
                    float vv[4];
                    #pragma unroll
                    for (int j = 0; j < 4; ++j) vv[j] = ip[j];
                    #pragma unroll
                    for (int j = 0; j < 4; ++j)
                        #pragma unroll
                        for (int i = 0; i < 8; ++i) acc[j][i] += vv[j] * wv[i];
                }
            }
        }
    }
    const int orow = r0 + row;
    #pragma unroll
    for (int i = 0; i < 8; ++i) {
        int co = ty * 8 + i;
        float b = bias[co];
        float s = bnp[co] * rsqrtf(bnp[192 + co] + 1e-5f);
        float m = bnp[128 + co], bt = bnp[64 + co];
        float r[4];
        #pragma unroll
        for (int j = 0; j < 4; ++j) {
            r[j] = (acc[j][i] + b - m) * s + bt;
            if (RELU) r[j] = fmaxf(r[j], 0.f);
        }
        float4 o; o.x = r[0]; o.y = r[1]; o.z = r[2]; o.w = r[3];
        *(float4*)&out[((size_t)n * 64 + co) * (OW * OW) + orow * OW + col4] = o;
    }
}

// =====================================================================
// conv-transpose k4 s2 p1, CIN=64. Zero-padded halo rows -> branch-free
// 4-tap inner loop. Tile = R rows x OUTW cols (full width) x all co.
// =====================================================================
template<int COUT, int OUTW, int R, bool PRERELU, bool TANH_LOSS>
__global__ __launch_bounds__(256) void convt_t(
    const float* __restrict__ in, float* __restrict__ out,
    const float* __restrict__ w, const float* __restrict__ bias,
    const float* __restrict__ xref)
{
    constexpr int HIN = OUTW / 2;
    constexpr int NRW = R + 1;
    constexpr int NC  = OUTW / 2 + 2;
    constexpr int NCP = (NC & 1) ? NC : NC + 1;
    constexpr int SPT = R * OUTW;
    constexpr int TXN = SPT / 4;
    constexpr int COS = (COUT == 64) ? 64 : 16;
    __shared__ float sIn[8 * NRW * NCP];
    __shared__ float sW [8 * 16 * 68];
    const int t = threadIdx.x, ty = t / TXN, tx = t % TXN;
    const int row = tx / (OUTW / 4), col4 = (tx % (OUTW / 4)) * 4;
    const int n = blockIdx.y, r0 = blockIdx.x * R;
    const int base_hi = ((r0 + 1) >> 1) - 1;
    const float* inb = in + (size_t)n * 64 * HIN * HIN;
    const int ho = r0 + row;
    const int kh_a = (ho + 1) & 1;
    const int rr_a = ((ho + 1) >> 1) - base_hi;
    int cc0[4], kwp[4];
    #pragma unroll
    for (int j = 0; j < 4; ++j) {
        int wo = col4 + j;
        kwp[j] = (wo + 1) & 1;
        cc0[j] = ((wo + 1) >> 1) + 1;     // - base_wi (= -1)
    }
    float acc[4][8];
    #pragma unroll
    for (int j = 0; j < 4; ++j)
        #pragma unroll
        for (int i = 0; i < 8; ++i) acc[j][i] = 0.f;

    for (int ci0 = 0; ci0 < 64; ci0 += 8) {
        __syncthreads();
        for (int i = t; i < 8 * NRW * NCP; i += 256) {
            int ci = i / (NRW * NCP), r2 = i - ci * NRW * NCP;
            int rr = r2 / NCP, cc = r2 - rr * NCP;
            int gr = base_hi + rr, gc = cc - 1;
            float v = 0.f;
            if ((unsigned)gr < (unsigned)HIN && (unsigned)gc < (unsigned)HIN) {
                v = inb[(ci0 + ci) * (HIN * HIN) + gr * HIN + gc];
                if (PRERELU) v = fmaxf(v, 0.f);
            }
            sIn[i] = v;
        }
        for (int i = t; i < 8 * 16 * COS; i += 256) {
            int ci = i / (16 * COS), r2 = i - ci * 16 * COS;
            int co = r2 >> 4, tap = r2 & 15;
            float v = (co < COUT) ? w[((ci0 + ci) * COUT + co) * 16 + tap] : 0.f;
            sW[ci * 1088 + tap * 68 + co] = v;
        }
        __syncthreads();
        #pragma unroll
        for (int ci = 0; ci < 8; ++ci) {
            const float* rA = sIn + ci * (NRW * NCP) + rr_a * NCP;
            const float* rB = rA - NCP;
            const float* sWb = sW + ci * 1088 + ty * 8;
            #pragma unroll
            for (int jp = 0; jp < 2; ++jp) {
                int t0 = kh_a * 4 + kwp[jp];
                float wv[4][8];
                #pragma unroll
                for (int k = 0; k < 4; ++k) {
                    int tap = t0 + (k & 1) * 2 + (k >> 1) * 8;
                    *(float4*)&wv[k][0] = *(const float4*)(sWb + tap * 68);
                    *(float4*)&wv[k][4] = *(const float4*)(sWb + tap * 68 + 4);
                }
                #pragma unroll
                for (int jj = 0; jj < 2; ++jj) {
                    int j = jp + jj * 2;
                    int ca = cc0[j], cb = ca - 1;
                    float vaa = rA[ca], vab = rA[cb], vba = rB[ca], vbb = rB[cb];
                    #pragma unroll
                    for (int i = 0; i < 8; ++i)
                        acc[j][i] += vaa * wv[0][i] + vab * wv[1][i]
                                   + vba * wv[2][i] + vbb * wv[3][i];
                }
            }
        }
    }
    float ls = 0.f;
    #pragma unroll
    for (int i = 0; i < 8; ++i) {
        int co = ty * 8 + i;
        if (co < COUT) {
            float b = bias[co];
            size_t oi = ((size_t)n * COUT + co) * ((size_t)OUTW * OUTW) + ho * OUTW + col4;
            float r[4];
            #pragma unroll
            for (int j = 0; j < 4; ++j) {
                r[j] = acc[j][i] + b;
                if (TANH_LOSS) {
                    r[j] = tanhf(r[j]);
                    float d = r[j] - xref[oi + j];
                    ls += d * d;
                } else {
                    r[j] = fmaxf(r[j], 0.f);
                }
            }
            float4 o; o.x = r[0]; o.y = r[1]; o.z = r[2]; o.w = r[3];
            *(float4*)&out[oi] = o;
        }
    }
    if (TANH_LOSS) {
        float s = block_sum(ls);
        if (t == 0) atomicAdd(&g_recon_ss, (double)s);
    }
}

// ---------------- VQ ----------------
__global__ void cnorm_k(const float* __restrict__ cb) {
    int k = blockIdx.x * 256 + threadIdx.x;
    if (k < 2048) {
        float s = 0.f;
        #pragma unroll
        for (int d = 0; d < 64; ++d) { float c = cb[k * 64 + d]; s += c * c; }
        g_cnorm[k] = s;
    }
}

__global__ __launch_bounds__(256) void vq_assign_k(
    const float* __restrict__ z, const float* __restrict__ cb)
{
    __shared__ float4 sc[128 * 16];
    __shared__ float  sn[128];
    int row = blockIdx.x * 256 + threadIdx.x;
    int b = row >> 10, hw = row & 1023;
    float zr[64];
    const float* zp = z + ((size_t)b * 64) * 1024 + hw;
    #pragma unroll
    for (int d = 0; d < 64; ++d) zr[d] = zp[d * 1024];
    float best = 3.4e38f; int bi = 0;
    const float4* cb4 = (const float4*)cb;
    for (int k0 = 0; k0 < 2048; k0 += 128) {
        __syncthreads();
        for (int i = threadIdx.x; i < 128 * 16; i += 256) sc[i] = cb4[k0 * 16 + i];
        for (int i = threadIdx.x; i < 128; i += 256) sn[i] = g_cnorm[k0 + i];
        __syncthreads();
        for (int kk = 0; kk < 128; ++kk) {
            const float4* cp = sc + kk * 16;
            float dot = 0.f;
            #pragma unroll
            for (int j = 0; j < 16; ++j) {
                float4 c = cp[j];
                dot += zr[4 * j] * c.x + zr[4 * j + 1] * c.y
                     + zr[4 * j + 2] * c.z + zr[4 * j + 3] * c.w;
            }
            float dist = sn[kk] - 2.f * dot;
            if (dist < best) { best = dist; bi = k0 + kk; }
        }
    }
    g_idx[row] = bi;
}

__global__ __launch_bounds__(256) void vq_gather_k(
    const float* __restrict__ z, const float* __restrict__ cb,
    float* __restrict__ quant)
{
    int gid = blockIdx.x * 256 + threadIdx.x;
    int b = gid >> 16;
    int rem = gid & 65535;
    int d = rem >> 10;
    int hw = rem & 1023;
    int k = g_idx[(b << 10) + hw];
    float q = cb[k * 64 + d];
    float zv = z[gid];
    quant[gid] = q;
    float diff = q - zv;
    float s = block_sum(diff * diff);
    if (threadIdx.x == 0) atomicAdd(&g_vq_ss, (double)s);
}

__global__ void vq_counts_k() {
    int i = blockIdx.x * 256 + threadIdx.x;
    if (i < 32768) atomicAdd(&g_counts[g_idx[i]], 1.0f);
}

// ---------------- finalize ----------------
__global__ void finalize_k(float* __restrict__ out2) {
    float s = 0.f;
    for (int k = threadIdx.x; k < 2048; k += 256) {
        float p = g_counts[k] * (1.0f / 32768.0f);
        s += p * logf(p + 1e-10f);
    }
    float tot = block_sum(s);
    if (threadIdx.x == 0) {
        float perp = expf(-tot);
        float loss = (float)(g_recon_ss / 31457280.0 + 1.25 * (g_vq_ss / 2097152.0));
        out2[0] = loss;
        out2[1] = perp;
    }
}

// ---------------- launcher ----------------
extern "C" void kernel_launch(void* const* d_in, const int* in_sizes, int n_in,
                              void* d_out, int out_size) {
    const float* x          = (const float*)d_in[0];
    const float* ew1        = (const float*)d_in[1];
    const float* eb1        = (const float*)d_in[2];
    const float* ew2        = (const float*)d_in[3];
    const float* eb2        = (const float*)d_in[4];
    const float* ew3        = (const float*)d_in[5];
    const float* eb3        = (const float*)d_in[6];
    const float* enc_bn     = (const float*)d_in[7];
    const float* enc_res_w3 = (const float*)d_in[8];
    const float* enc_res_b3 = (const float*)d_in[9];
    const float* enc_res_w1 = (const float*)d_in[10];
    const float* enc_res_b1 = (const float*)d_in[11];
    const float* enc_res_bn = (const float*)d_in[12];
    const float* enc_out_w  = (const float*)d_in[13];
    const float* enc_out_b  = (const float*)d_in[14];
    const float* codebook   = (const float*)d_in[15];
    const float* dec_in_w   = (const float*)d_in[16];
    const float* dec_in_b   = (const float*)d_in[17];
    const float* dec_res_w3 = (const float*)d_in[18];
    const float* dec_res_b3 = (const float*)d_in[19];
    const float* dec_res_w1 = (const float*)d_in[20];
    const float* dec_res_b1 = (const float*)d_in[21];
    const float* dec_res_bn = (const float*)d_in[22];
    const float* dt_w1      = (const float*)d_in[23];
    const float* dt_b1      = (const float*)d_in[24];
    const float* dt_w2      = (const float*)d_in[25];
    const float* dt_b2      = (const float*)d_in[26];
    const float* dt_w3      = (const float*)d_in[27];
    const float* dt_b3      = (const float*)d_in[28];

    void *pa, *pb, *pc;
    cudaGetSymbolAddress(&pa, g_bufA);
    cudaGetSymbolAddress(&pb, g_bufB);
    cudaGetSymbolAddress(&pc, g_bufC);
    float* A  = (float*)pa;
    float* Bb = (float*)pb;
    float* Cc = (float*)pc;
    float* out = (float*)d_out;

    init_k<<<8, 256>>>();

    // ---- Encoder ----
    conv4s2_t<15, 128, 5, true ><<<dim3(128, 32), 256>>>(x,  A,  ew1, eb1, enc_bn);
    conv4s2_t<64, 64,  4, true ><<<dim3(32, 32),  256>>>(A,  Bb, ew2, eb2, enc_bn + 256);
    conv4s2_t<64, 32,  4, false><<<dim3(8, 32),   256>>>(Bb, A,  ew3, eb3, enc_bn + 512);
    for (int i = 0; i < 4; ++i) {
        conv3x3_t<true, true><<<dim3(8, 32), 256>>>(
            A, Bb, enc_res_w3 + (size_t)i * 36864, enc_res_b3 + i * 64,
            enc_res_bn + i * 512);
        conv1x1_t<true, true, true><<<dim3(8, 32), 256>>>(
            Bb, A, A, enc_res_w1 + (size_t)i * 4096, enc_res_b1 + i * 64,
            enc_res_bn + i * 512 + 256);
    }
    conv1x1_t<false, false, false><<<dim3(8, 32), 256>>>(
        A, nullptr, Bb, enc_out_w, enc_out_b, nullptr);     // z -> Bb

    // ---- VQ ----
    cnorm_k<<<8, 256>>>(codebook);
    vq_assign_k<<<128, 256>>>(Bb, codebook);
    vq_gather_k<<<8192, 256>>>(Bb, codebook, A);            // quant -> A
    vq_counts_k<<<128, 256>>>();

    // ---- Decoder ----
    conv3x3_t<false, false><<<dim3(8, 32), 256>>>(A, Bb, dec_in_w, dec_in_b, nullptr);
    for (int i = 0; i < 4; ++i) {
        conv3x3_t<true, true><<<dim3(8, 32), 256>>>(
            Bb, Cc, dec_res_w3 + (size_t)i * 36864, dec_res_b3 + i * 64,
            dec_res_bn + i * 512);
        conv1x1_t<true, true, true><<<dim3(8, 32), 256>>>(
            Cc, Bb, Bb, dec_res_w1 + (size_t)i * 4096, dec_res_b1 + i * 64,
            dec_res_bn + i * 512 + 256);
    }
    convt_t<64, 64,  2, true,  false><<<dim3(32, 32),  256>>>(Bb, A,   dt_w1, dt_b1, nullptr);
    convt_t<64, 128, 1, false, false><<<dim3(128, 32), 256>>>(A,  Bb,  dt_w2, dt_b2, nullptr);
    convt_t<15, 256, 2, false, true ><<<dim3(128, 32), 256>>>(Bb, out, dt_w3, dt_b3, x);

    finalize_k<<<1, 256>>>(out + (out_size - 2));
}